// round 14
// baseline (speedup 1.0000x reference)
#include <cuda_runtime.h>

namespace {

constexpr int BATCH   = 4;
constexpr int NIN     = 1024;
constexpr int NOUT    = 1024;
constexpr int CH      = 8;     // density + 7 raw channels
constexpr int OC      = 16;
constexpr int OPB     = 64;    // outputs per block (2 half-tiles of 32)
constexpr int SPLITS  = 8;     // i-dimension splits across blocks
constexpr int ISPB    = NIN / SPLITS;      // 128 i per block
constexpr int THREADS = 256;
constexpr int WARPS   = THREADS / 32;      // 8
constexpr int ISLICES = 4;                 // i-slices per otile half
constexpr int IPW     = ISPB / ISLICES;    // 32 i per warp
constexpr int NTILES  = NOUT / OPB;        // 16

// Partial aggregates: [b*1024+O][split][c]  (1 MB scratch)
__device__ float g_part[BATCH * NOUT * SPLITS * CH];
// Per-otile completion counters (zero-init; finisher resets -> replay-safe)
__device__ int   g_count[BATCH * NTILES];

__device__ __forceinline__ float ex2_approx(float x) {
    float y;
    asm("ex2.approx.f32 %0, %1;" : "=f"(y) : "f"(x));
    return y;
}

// --------- Fused kernel: partial aggregation + last-block finish ---------
// (256, 5): 48-reg budget (validated for the scalar-FMA body in R12)
__global__ __launch_bounds__(THREADS, 5)
void convdeepset_kernel(const float* __restrict__ cx,     // [B, NIN, 1]
                        const float* __restrict__ cy,     // [B, NIN, 7]
                        const float* __restrict__ t,      // [B, NOUT, 1]
                        const float* __restrict__ sigma,  // [8]
                        const float* __restrict__ W,      // [8, 16]
                        const float* __restrict__ bias,   // [16]
                        float* __restrict__ out)          // [B*NOUT, 16]
{
    // sy[i] = [y1..y7, 1.0] -> two broadcast LDS.128 per i
    __shared__ float  sy[ISPB][CH];              // 4 KB
    __shared__ float  sx[ISPB];                  // 0.5 KB (pre-scaled x)
    __shared__ float  spart[ISLICES][OPB][CH];   // 8 KB
    __shared__ float  sagg2[OPB][CH];            // 2 KB (finisher only)
    __shared__ float  sbeta[CH];
    __shared__ float  skscale;
    __shared__ int    suni;
    __shared__ int    s_last;

    const int bi    = blockIdx.x;
    const int b     = bi >> 7;                   // / (NTILES*SPLITS)
    const int otile = (bi >> 3) & 15;
    const int split = bi & 7;
    const int tid   = threadIdx.x;
    const int warp  = tid >> 5;
    const int lane  = tid & 31;
    const int i0    = split * ISPB;

    // ---- singleton prologue: betas, kscale, uniformity flag ----
    if (tid == 0) {
        const float L2E = 1.4426950408889634f;
        int u = 1;
        float sg0 = sigma[0];
        #pragma unroll
        for (int c = 0; c < CH; c++) {
            float sgc = sigma[c];
            float s = expf(sgc);
            sbeta[c] = -0.5f * L2E / (s * s);
            u &= (sgc == sg0);
        }
        suni = u;
        skscale = sqrtf(0.5f * L2E) / expf(sg0);
    }
    __syncthreads();

    const float kscale = skscale;

    // ---- stage y (density=1.0 in slot 7) and pre-scaled x ----
    #pragma unroll
    for (int r = 0; r < 4; r++) {
        int idx = tid + r * THREADS;             // 0..1023
        int i = idx >> 3, c = idx & 7;
        sy[i][c] = (c < 7) ? cy[(b * NIN + i0 + i) * 7 + c] : 1.0f;
    }
    if (tid < ISPB) sx[tid] = kscale * cx[b * NIN + i0 + tid];

    const int oth = warp >> 2;                   // otile half: 0 or 1
    const int isl = warp & 3;                    // i-slice within the half
    const int G0  = b * NOUT + otile * OPB;
    const float t_k = kscale * t[G0 + oth * 32 + lane];
    __syncthreads();

    const bool uni = (suni != 0);

    // Accumulators in y-slot order: [y1..y7, den]
    float acc[CH];
    #pragma unroll
    for (int c = 0; c < CH; c++) acc[c] = 0.0f;

    const float4* xw4 = reinterpret_cast<const float4*>(&sx[isl * IPW]);
    const float4* yw  = reinterpret_cast<const float4*>(&sy[isl * IPW][0]);

    if (uni) {
        #pragma unroll
        for (int jc = 0; jc < IPW / 4; jc++) {
            // 4 independent exp chains (MUFU pipelines at rt=8)
            float4 x4 = xw4[jc];                 // one LDS.128
            float d0 = x4.x - t_k;
            float d1 = x4.y - t_k;
            float d2 = x4.z - t_k;
            float d3 = x4.w - t_k;
            float w0 = ex2_approx(d0 * -d0);     // neg folds into FMUL
            float w1 = ex2_approx(d1 * -d1);
            float w2 = ex2_approx(d2 * -d2);
            float w3 = ex2_approx(d3 * -d3);
            #pragma unroll
            for (int u = 0; u < 4; u++) {
                int j = jc * 4 + u;
                float w = (u == 0) ? w0 : (u == 1) ? w1 : (u == 2) ? w2 : w3;
                float4 p0 = yw[2 * j];           // {y1,y2,y3,y4} broadcast
                float4 p1 = yw[2 * j + 1];       // {y5,y6,y7,1}
                acc[0] += p0.x * w;  acc[1] += p0.y * w;
                acc[2] += p0.z * w;  acc[3] += p0.w * w;
                acc[4] += p1.x * w;  acc[5] += p1.y * w;
                acc[6] += p1.z * w;  acc[7] += w;        // density: y==1
            }
        }
    } else {
        // General path: exponent_c = (beta_c/beta0) * a, a = beta0*d_raw^2
        float ratio[CH];
        #pragma unroll
        for (int c = 0; c < CH; c++) ratio[c] = sbeta[c] / sbeta[0];
        const float* yws = &sy[isl * IPW][0];
        const float* xw  = &sx[isl * IPW];
        #pragma unroll 2
        for (int j = 0; j < IPW; j++) {
            float d = xw[j] - t_k;
            float a = d * -d;                    // = beta0 * d_raw^2
            #pragma unroll
            for (int c = 0; c < 7; c++)
                acc[c] += yws[j * CH + c] * ex2_approx(ratio[c + 1] * a);
            acc[7] += ex2_approx(ratio[0] * a);  // density
        }
    }

    // Per-warp partials in canonical order [den, y1..y7]
    {
        int o = oth * 32 + lane;
        *reinterpret_cast<float4*>(&spart[isl][o][0]) =
            make_float4(acc[7], acc[0], acc[1], acc[2]);
        *reinterpret_cast<float4*>(&spart[isl][o][4]) =
            make_float4(acc[3], acc[4], acc[5], acc[6]);
    }
    __syncthreads();

    // Cross-slice reduce: 512 (o,c) slots over 256 threads (2 each)
    #pragma unroll
    for (int rr = 0; rr < 2; rr++) {
        int idx = tid + rr * THREADS;
        int o = idx >> 3, c = idx & 7;
        float s = spart[0][o][c] + spart[1][o][c]
                + spart[2][o][c] + spart[3][o][c];
        g_part[((G0 + o) * SPLITS + split) * CH + c] = s;
    }

    // ---- last-block-done gate (threadFenceReduction pattern) ----
    __threadfence();
    if (tid == 0) {
        int old = atomicAdd(&g_count[b * NTILES + otile], 1);
        s_last = (old == SPLITS - 1);
        if (s_last) g_count[b * NTILES + otile] = 0;   // reset for replay
    }
    __syncthreads();
    if (!s_last) return;

    // ---- finish: combine splits + normalize (2 slots per thread) ----
    #pragma unroll
    for (int rr = 0; rr < 2; rr++) {
        int idx = tid + rr * THREADS;
        int o = idx >> 3, c = idx & 7;
        const float* p = &g_part[((G0 + o) * SPLITS) * CH + c];
        float s = 0.0f;
        #pragma unroll
        for (int sp = 0; sp < SPLITS; sp++) s += p[sp * CH];
        float den = __shfl_sync(0xffffffffu, s, lane & ~7u);
        sagg2[o][c] = (c == 0) ? s : s / (den + 1e-8f);
    }
    __syncthreads();

    // ---- finish: out[G][k] = bias[k] + sum_c agg2[c] * W[c][k] ----
    #pragma unroll
    for (int rr = 0; rr < 4; rr++) {
        int idx = tid + rr * THREADS;                 // 0..1023
        int o = idx >> 4, k = idx & 15;
        float v = __ldg(&bias[k]);
        #pragma unroll
        for (int c = 0; c < CH; c++) v += sagg2[o][c] * __ldg(&W[c * OC + k]);
        out[(G0 + o) * OC + k] = v;                   // coalesced
    }
}

} // namespace

extern "C" void kernel_launch(void* const* d_in, const int* in_sizes, int n_in,
                              void* d_out, int out_size) {
    const float* cx = (const float*)d_in[0];  // context_x
    const float* cy = (const float*)d_in[1];  // context_y
    const float* t  = (const float*)d_in[2];  // t
    const float* sg = (const float*)d_in[3];  // sigma
    const float* W  = (const float*)d_in[4];  // W
    const float* bi = (const float*)d_in[5];  // b
    float* out = (float*)d_out;

    convdeepset_kernel<<<BATCH * NTILES * SPLITS, THREADS>>>(cx, cy, t, sg, W, bi, out);
}